// round 8
// baseline (speedup 1.0000x reference)
#include <cuda_runtime.h>

#define H    512
#define MT   32          // points per block
#define NT   1024        // threads per block (32 warps, 8 per SMSP)
#define SROW 36          // padded m-stride of transposed activation tiles (144B, 16B-aligned rows)

typedef unsigned long long ull;

// ---- packed fp32x2 helpers (sm_100+) ----
__device__ __forceinline__ ull pack2s(float x){
    ull r; asm("mov.b64 %0, {%1, %1};" : "=l"(r) : "f"(x)); return r;
}
__device__ __forceinline__ float2 unpack2(ull v){
    float2 f; asm("mov.b64 {%0, %1}, %2;" : "=f"(f.x), "=f"(f.y) : "l"(v)); return f;
}
__device__ __forceinline__ void fma2(ull &d, ull a, ull b){
    asm("fma.rn.f32x2 %0, %1, %2, %0;" : "+l"(d) : "l"(a), "l"(b));
}

__device__ __forceinline__ void acc_zero(ull acc[4][2]){
#pragma unroll
    for (int r = 0; r < 4; ++r)
#pragma unroll
        for (int c = 0; c < 2; ++c) acc[r][c] = 0ull;
}

// acc[4 row-pairs][2 cols] += S^T[32 x H] (stored [k][m], stride SROW) @ W[HxH]
// thread: rows mbase..mbase+7 (4 f32x2 pairs), cols n0..n0+1.
// S: 2 broadcast LDS.128 per k (pre-packed row-pair f32x2).
// W: one float2 LDG per k, depth-3 ring; prefetch index wraps with &(H-1)
// (always in-bounds, 1 LOP instead of SEL+IMAD clamp).
__device__ __forceinline__ void gemmT(const float* __restrict__ S,
                                      const float* __restrict__ W,
                                      ull acc[4][2], int mbase, int tcol)
{
    const float2* __restrict__ W2 = reinterpret_cast<const float2*>(W); // 256 per row
    float2 w0 = W2[tcol];
    float2 w1 = W2[256 + tcol];
    float2 w2 = W2[512 + tcol];
#pragma unroll 8
    for (int k = 0; k < H; ++k){
        const int kn = (k + 3) & (H - 1);
        float2 wn = W2[kn * 256 + tcol];
        const ulonglong2 sA = *reinterpret_cast<const ulonglong2*>(S + k*SROW + mbase);
        const ulonglong2 sB = *reinterpret_cast<const ulonglong2*>(S + k*SROW + mbase + 4);
        const ull wd0 = pack2s(w0.x);
        const ull wd1 = pack2s(w0.y);
        fma2(acc[0][0], sA.x, wd0); fma2(acc[1][0], sA.y, wd0);
        fma2(acc[2][0], sB.x, wd0); fma2(acc[3][0], sB.y, wd0);
        fma2(acc[0][1], sA.x, wd1); fma2(acc[1][1], sA.y, wd1);
        fma2(acc[2][1], sB.x, wd1); fma2(acc[3][1], sB.y, wd1);
        w0 = w1; w1 = w2; w2 = wn;
    }
}

extern "C" __global__ void __launch_bounds__(NT, 1)
fcblock_kernel(const float* __restrict__ coords,
               const float* __restrict__ Wu0,  const float* __restrict__ bu0,
               const float* __restrict__ Wu,   const float* __restrict__ bu,
               const float* __restrict__ Wzuu, const float* __restrict__ bzuu,
               const float* __restrict__ Wzzu, const float* __restrict__ Wzzu_last,
               const float* __restrict__ Wyuu0,const float* __restrict__ byuu0,
               const float* __restrict__ Wyuu, const float* __restrict__ byuu,
               const float* __restrict__ Wzyu, const float* __restrict__ Wzyu_last,
               const float* __restrict__ Wzu0, const float* __restrict__ bzu0,
               const float* __restrict__ Wzu,  const float* __restrict__ bzu,
               const float* __restrict__ Wzu_last, const float* __restrict__ bzu_last,
               const float* __restrict__ pp, const float* __restrict__ ppu,
               const float* __restrict__ ppzu,
               float* __restrict__ out, int Npts)
{
    extern __shared__ float smem[];
    float* suT  = smem;                     // [H][SROW]  u, transposed
    float* szT  = suT + H * SROW;           // [H][SROW]  z / zz, transposed
    float* sc   = szT + H * SROW;           // [MT*4]     raw coords
    float* syy  = sc + MT * 4;              // [MT]       per-row y-term
    float* sred = syy + MT;                 // [3*NT]     reduction scratch

    const int tid   = threadIdx.x;
    const int trow  = tid >> 8;             // 0..3
    const int tcol  = tid & 255;            // 0..255
    const int mbase = trow * 8;
    const int n0    = tcol * 2;
    const int m0    = blockIdx.x * MT;

    const float P   = 10.f * pp[0];
    const float PU  = 10.f * ppu[0];
    const float PZU = 10.f * ppzu[0];

    if (tid < MT * 4){
        const int gidx = m0 * 4 + tid;
        sc[tid] = (gidx < Npts * 4) ? coords[gidx] : 0.f;
    }
    __syncthreads();

    // ---------------- stage 0 (K = 3), write transposed ----------------
#pragma unroll
    for (int c = 0; c < 2; ++c){
        const int n = n0 + c;
        const float wz0 = Wzu0[n], wz1 = Wzu0[H+n], wz2 = Wzu0[2*H+n];
        const float wu0v = Wu0[n], wu1v = Wu0[H+n], wu2v = Wu0[2*H+n];
        const float bz = bzu0[n], buv = bu0[n], wy = Wzyu[n];
#pragma unroll
        for (int r = 0; r < 8; ++r){
            const int m = mbase + r;
            const float a0 = sc[m*4+0], a1 = sc[m*4+1], a2 = sc[m*4+2], y = sc[m*4+3];
            const float s0 = a0*Wyuu0[0] + a1*Wyuu0[1] + a2*Wyuu0[2] + byuu0[0];
            const float ys = y * s0;
            const float zv = a0*wz0 + a1*wz1 + a2*wz2 + bz + ys*wy;
            const float uv = a0*wu0v + a1*wu1v + a2*wu2v + buv;
            szT[n*SROW + m] = fmaxf(P  * zv, 0.f);
            suT[n*SROW + m] = fmaxf(PU * uv, 0.f);
        }
    }
    __syncthreads();

    // ---------------- stages 1..2 ----------------
#pragma unroll 1
    for (int i = 1; i <= 2; ++i){
        const float* Wzuu_i = Wzuu + (i-1)*H*H;
        const float* bzuu_i = bzuu + (i-1)*H;
        const float* Wzzu_i = Wzzu + (i-1)*H*H;
        const float* Wzu_i  = Wzu  + (i-1)*H*H;
        const float* bzu_i  = bzu  + (i-1)*H;
        const float* Wu_i   = Wu   + (i-1)*H*H;
        const float* bu_i   = bu   + (i-1)*H;
        const float* Wyuu_i = Wyuu + (i-1)*H;
        const float  byuu_i = byuu[i-1];
        const float* Wzyu_i = Wzyu + i*H;

        ull acc[4][2];

        // (a) gate = relu(PZU*(u@Wzuu+bzuu)); zz = z*gate (in place in szT)
        acc_zero(acc);
        gemmT(suT, Wzuu_i, acc, mbase, tcol);
#pragma unroll
        for (int c = 0; c < 2; ++c){
            const int n = n0 + c;
            const float bz = bzuu_i[n];
            float* zrow = szT + n*SROW + mbase;
#pragma unroll
            for (int rp = 0; rp < 4; ++rp){
                float2 v = unpack2(acc[rp][c]);
                zrow[2*rp]   *= fmaxf(PZU * (v.x + bz), 0.f);
                zrow[2*rp+1] *= fmaxf(PZU * (v.y + bz), 0.f);
            }
        }
        // partial dot s[m] = u[m,:].Wyuu_i  (32 segments of 16 k)
        {
            const int rrow = tid >> 5, rseg = tid & 31;   // rrow 0..31, rseg 0..31
            float ps = 0.f;
#pragma unroll 8
            for (int j = 0; j < 16; ++j){
                const int k = rseg + 32*j;
                ps += suT[k*SROW + rrow] * Wyuu_i[k];
            }
            sred[rseg * 32 + rrow] = ps;
        }
        __syncthreads();          // zz + partials visible

        // warp 0 folds partials into per-row y-term
        if (tid < MT){
            float s = 0.f;
#pragma unroll
            for (int sgi = 0; sgi < 32; ++sgi) s += sred[sgi*32 + tid];
            syy[tid] = sc[tid*4+3] * (s + byuu_i);
        }

        // (b) znew = zz@Wzzu + u@Wzu (+bias + y-term)
        acc_zero(acc);
        gemmT(szT, Wzzu_i, acc, mbase, tcol);
        gemmT(suT, Wzu_i,  acc, mbase, tcol);
        __syncthreads();          // all zz reads done; syy visible
#pragma unroll
        for (int c = 0; c < 2; ++c){
            const int n = n0 + c;
            const float bz = bzu_i[n], wy = Wzyu_i[n];
            float* zrow = szT + n*SROW + mbase;
#pragma unroll
            for (int rp = 0; rp < 4; ++rp){
                float2 v = unpack2(acc[rp][c]);
                const int m = mbase + 2*rp;
                zrow[2*rp]   = fmaxf(P * (v.x + bz + syy[m]   * wy), 0.f);
                zrow[2*rp+1] = fmaxf(P * (v.y + bz + syy[m+1] * wy), 0.f);
            }
        }

        // (c) unew = relu(PU*(u@Wu+bu))
        acc_zero(acc);
        gemmT(suT, Wu_i, acc, mbase, tcol);
        __syncthreads();          // all u reads done
#pragma unroll
        for (int c = 0; c < 2; ++c){
            const int n = n0 + c;
            const float bv = bu_i[n];
            float* urow = suT + n*SROW + mbase;
#pragma unroll
            for (int rp = 0; rp < 4; ++rp){
                float2 v = unpack2(acc[rp][c]);
                urow[2*rp]   = fmaxf(PU * (v.x + bv), 0.f);
                urow[2*rp+1] = fmaxf(PU * (v.y + bv), 0.f);
            }
        }
        __syncthreads();
    }

    // ---------------- final stage ----------------
    {
        const float* Wzuu2 = Wzuu + 2*H*H;
        const float* bzuu2 = bzuu + 2*H;
        const float* Wyuu2 = Wyuu + 2*H;

        ull acc[4][2];
        acc_zero(acc);
        gemmT(suT, Wzuu2, acc, mbase, tcol);
#pragma unroll
        for (int c = 0; c < 2; ++c){
            const int n = n0 + c;
            const float bz = bzuu2[n];
            float* zrow = szT + n*SROW + mbase;
#pragma unroll
            for (int rp = 0; rp < 4; ++rp){
                float2 v = unpack2(acc[rp][c]);
                zrow[2*rp]   *= fmaxf(PZU * (v.x + bz), 0.f);
                zrow[2*rp+1] *= fmaxf(PZU * (v.y + bz), 0.f);
            }
        }
        __syncthreads();

        // three K=512 dots per point (32 segments of 16)
        const int rrow = tid >> 5, rseg = tid & 31;
        float p1 = 0.f, p2 = 0.f, p3 = 0.f;
#pragma unroll 8
        for (int j = 0; j < 16; ++j){
            const int k = rseg + 32*j;
            const float uk = suT[k*SROW + rrow];
            const float zk = szT[k*SROW + rrow];
            p1 += zk * Wzzu_last[k];
            p2 += uk * Wzu_last[k];
            p3 += uk * Wyuu2[k];
        }
        const int ridx = rseg * 32 + rrow;
        sred[ridx]          = p1;
        sred[NT + ridx]     = p2;
        sred[2*NT + ridx]   = p3;
        __syncthreads();

        if (tid < MT && (m0 + tid) < Npts){
            float s1 = 0.f, s2 = 0.f, s3 = 0.f;
#pragma unroll
            for (int sgi = 0; sgi < 32; ++sgi){
                s1 += sred[sgi*32 + tid];
                s2 += sred[NT + sgi*32 + tid];
                s3 += sred[2*NT + sgi*32 + tid];
            }
            out[m0 + tid] = s1 + s2 + bzu_last[0]
                          + sc[tid*4+3] * (s3 + byuu[2]) * Wzyu_last[0];
        }
    }
}

extern "C" void kernel_launch(void* const* d_in, const int* in_sizes, int n_in,
                              void* d_out, int out_size)
{
    const float* coords    = (const float*)d_in[0];
    const float* Wu0       = (const float*)d_in[1];
    const float* bu0       = (const float*)d_in[2];
    const float* Wu        = (const float*)d_in[3];
    const float* bu        = (const float*)d_in[4];
    const float* Wzuu      = (const float*)d_in[5];
    const float* bzuu      = (const float*)d_in[6];
    const float* Wzzu      = (const float*)d_in[7];
    const float* Wzzu_last = (const float*)d_in[8];
    const float* Wyuu0     = (const float*)d_in[9];
    const float* byuu0     = (const float*)d_in[10];
    const float* Wyuu      = (const float*)d_in[11];
    const float* byuu      = (const float*)d_in[12];
    const float* Wzyu      = (const float*)d_in[13];
    const float* Wzyu_last = (const float*)d_in[14];
    const float* Wzu0      = (const float*)d_in[15];
    const float* bzu0      = (const float*)d_in[16];
    const float* Wzu       = (const float*)d_in[17];
    const float* bzu       = (const float*)d_in[18];
    const float* Wzu_last  = (const float*)d_in[19];
    const float* bzu_last  = (const float*)d_in[20];
    const float* pp        = (const float*)d_in[21];
    const float* ppu       = (const float*)d_in[22];
    const float* ppzu      = (const float*)d_in[23];
    float* out = (float*)d_out;

    const int N = in_sizes[0] / 4;          // coords is (N,4)
    const int grid = (N + MT - 1) / MT;
    const size_t smem_bytes = (size_t)(2*H*SROW + MT*4 + MT + 3*NT) * sizeof(float);

    cudaFuncSetAttribute(fcblock_kernel,
                         cudaFuncAttributeMaxDynamicSharedMemorySize,
                         (int)smem_bytes);

    fcblock_kernel<<<grid, NT, smem_bytes>>>(
        coords, Wu0, bu0, Wu, bu, Wzuu, bzuu, Wzzu, Wzzu_last,
        Wyuu0, byuu0, Wyuu, byuu, Wzyu, Wzyu_last,
        Wzu0, bzu0, Wzu, bzu, Wzu_last, bzu_last,
        pp, ppu, ppzu, out, N);
}

// round 9
// speedup vs baseline: 1.0014x; 1.0014x over previous
#include <cuda_runtime.h>

#define H    512
#define MT   32          // points per block
#define NT   1024        // threads per block (32 warps, 8 per SMSP)
#define SROW 36          // padded m-stride of transposed activation tiles (144B, 16B-aligned rows)

typedef unsigned long long ull;

// ---- packed fp32x2 helpers (sm_100+) ----
__device__ __forceinline__ ull pack2s(float x){
    ull r; asm("mov.b64 %0, {%1, %1};" : "=l"(r) : "f"(x)); return r;
}
__device__ __forceinline__ float2 unpack2(ull v){
    float2 f; asm("mov.b64 {%0, %1}, %2;" : "=f"(f.x), "=f"(f.y) : "l"(v)); return f;
}
__device__ __forceinline__ void fma2(ull &d, ull a, ull b){
    asm("fma.rn.f32x2 %0, %1, %2, %0;" : "+l"(d) : "l"(a), "l"(b));
}

__device__ __forceinline__ void acc_zero(ull acc[4][2]){
#pragma unroll
    for (int r = 0; r < 4; ++r)
#pragma unroll
        for (int c = 0; c < 2; ++c) acc[r][c] = 0ull;
}

// acc[4 row-pairs][2 cols] += S^T[32 x H] (stored [k][m], stride SROW) @ W[HxH]
// thread: rows mbase..mbase+7 (4 f32x2 pairs), cols n0..n0+1.
// S: 2 broadcast LDS.128 per k (pre-packed row-pair f32x2).
// W: one float2 LDG per k, depth-3 ring; prefetch index wraps with &(H-1)
// (always in-bounds, 1 LOP instead of SEL+IMAD clamp).
__device__ __forceinline__ void gemmT(const float* __restrict__ S,
                                      const float* __restrict__ W,
                                      ull acc[4][2], int mbase, int tcol)
{
    const float2* __restrict__ W2 = reinterpret_cast<const float2*>(W); // 256 per row
    float2 w0 = W2[tcol];
    float2 w1 = W2[256 + tcol];
    float2 w2 = W2[512 + tcol];
#pragma unroll 8
    for (int k = 0; k < H; ++k){
        const int kn = (k + 3) & (H - 1);
        float2 wn = W2[kn * 256 + tcol];
        const ulonglong2 sA = *reinterpret_cast<const ulonglong2*>(S + k*SROW + mbase);
        const ulonglong2 sB = *reinterpret_cast<const ulonglong2*>(S + k*SROW + mbase + 4);
        const ull wd0 = pack2s(w0.x);
        const ull wd1 = pack2s(w0.y);
        fma2(acc[0][0], sA.x, wd0); fma2(acc[1][0], sA.y, wd0);
        fma2(acc[2][0], sB.x, wd0); fma2(acc[3][0], sB.y, wd0);
        fma2(acc[0][1], sA.x, wd1); fma2(acc[1][1], sA.y, wd1);
        fma2(acc[2][1], sB.x, wd1); fma2(acc[3][1], sB.y, wd1);
        w0 = w1; w1 = w2; w2 = wn;
    }
}

extern "C" __global__ void __launch_bounds__(NT, 1)
fcblock_kernel(const float* __restrict__ coords,
               const float* __restrict__ Wu0,  const float* __restrict__ bu0,
               const float* __restrict__ Wu,   const float* __restrict__ bu,
               const float* __restrict__ Wzuu, const float* __restrict__ bzuu,
               const float* __restrict__ Wzzu, const float* __restrict__ Wzzu_last,
               const float* __restrict__ Wyuu0,const float* __restrict__ byuu0,
               const float* __restrict__ Wyuu, const float* __restrict__ byuu,
               const float* __restrict__ Wzyu, const float* __restrict__ Wzyu_last,
               const float* __restrict__ Wzu0, const float* __restrict__ bzu0,
               const float* __restrict__ Wzu,  const float* __restrict__ bzu,
               const float* __restrict__ Wzu_last, const float* __restrict__ bzu_last,
               const float* __restrict__ pp, const float* __restrict__ ppu,
               const float* __restrict__ ppzu,
               float* __restrict__ out, int Npts)
{
    extern __shared__ float smem[];
    float* suT  = smem;                     // [H][SROW]  u, transposed
    float* szT  = suT + H * SROW;           // [H][SROW]  z / zz, transposed
    float* sc   = szT + H * SROW;           // [MT*4]     raw coords
    float* syy  = sc + MT * 4;              // [MT]       per-row y-term
    float* sred = syy + MT;                 // [3*NT]     reduction scratch

    const int tid   = threadIdx.x;
    const int trow  = tid >> 8;             // 0..3
    const int tcol  = tid & 255;            // 0..255
    const int mbase = trow * 8;
    const int n0    = tcol * 2;
    const int m0    = blockIdx.x * MT;

    const float P   = 10.f * pp[0];
    const float PU  = 10.f * ppu[0];
    const float PZU = 10.f * ppzu[0];

    if (tid < MT * 4){
        const int gidx = m0 * 4 + tid;
        sc[tid] = (gidx < Npts * 4) ? coords[gidx] : 0.f;
    }
    __syncthreads();

    // ---------------- stage 0 (K = 3), write transposed ----------------
#pragma unroll
    for (int c = 0; c < 2; ++c){
        const int n = n0 + c;
        const float wz0 = Wzu0[n], wz1 = Wzu0[H+n], wz2 = Wzu0[2*H+n];
        const float wu0v = Wu0[n], wu1v = Wu0[H+n], wu2v = Wu0[2*H+n];
        const float bz = bzu0[n], buv = bu0[n], wy = Wzyu[n];
#pragma unroll
        for (int r = 0; r < 8; ++r){
            const int m = mbase + r;
            const float a0 = sc[m*4+0], a1 = sc[m*4+1], a2 = sc[m*4+2], y = sc[m*4+3];
            const float s0 = a0*Wyuu0[0] + a1*Wyuu0[1] + a2*Wyuu0[2] + byuu0[0];
            const float ys = y * s0;
            const float zv = a0*wz0 + a1*wz1 + a2*wz2 + bz + ys*wy;
            const float uv = a0*wu0v + a1*wu1v + a2*wu2v + buv;
            szT[n*SROW + m] = fmaxf(P  * zv, 0.f);
            suT[n*SROW + m] = fmaxf(PU * uv, 0.f);
        }
    }
    __syncthreads();

    // ---------------- stages 1..2 ----------------
#pragma unroll 1
    for (int i = 1; i <= 2; ++i){
        const float* Wzuu_i = Wzuu + (i-1)*H*H;
        const float* bzuu_i = bzuu + (i-1)*H;
        const float* Wzzu_i = Wzzu + (i-1)*H*H;
        const float* Wzu_i  = Wzu  + (i-1)*H*H;
        const float* bzu_i  = bzu  + (i-1)*H;
        const float* Wu_i   = Wu   + (i-1)*H*H;
        const float* bu_i   = bu   + (i-1)*H;
        const float* Wyuu_i = Wyuu + (i-1)*H;
        const float  byuu_i = byuu[i-1];
        const float* Wzyu_i = Wzyu + i*H;

        ull acc[4][2];

        // (a) gate = relu(PZU*(u@Wzuu+bzuu)); zz = z*gate (in place in szT)
        acc_zero(acc);
        gemmT(suT, Wzuu_i, acc, mbase, tcol);
#pragma unroll
        for (int c = 0; c < 2; ++c){
            const int n = n0 + c;
            const float bz = bzuu_i[n];
            float* zrow = szT + n*SROW + mbase;
#pragma unroll
            for (int rp = 0; rp < 4; ++rp){
                float2 v = unpack2(acc[rp][c]);
                zrow[2*rp]   *= fmaxf(PZU * (v.x + bz), 0.f);
                zrow[2*rp+1] *= fmaxf(PZU * (v.y + bz), 0.f);
            }
        }
        // partial dot s[m] = u[m,:].Wyuu_i  (32 segments of 16 k)
        {
            const int rrow = tid >> 5, rseg = tid & 31;   // rrow 0..31, rseg 0..31
            float ps = 0.f;
#pragma unroll 8
            for (int j = 0; j < 16; ++j){
                const int k = rseg + 32*j;
                ps += suT[k*SROW + rrow] * Wyuu_i[k];
            }
            sred[rseg * 32 + rrow] = ps;
        }
        __syncthreads();          // zz + partials visible

        // warp 0 folds partials into per-row y-term
        if (tid < MT){
            float s = 0.f;
#pragma unroll
            for (int sgi = 0; sgi < 32; ++sgi) s += sred[sgi*32 + tid];
            syy[tid] = sc[tid*4+3] * (s + byuu_i);
        }

        // (b) znew = zz@Wzzu + u@Wzu (+bias + y-term)
        acc_zero(acc);
        gemmT(szT, Wzzu_i, acc, mbase, tcol);
        gemmT(suT, Wzu_i,  acc, mbase, tcol);
        __syncthreads();          // all zz reads done; syy visible
#pragma unroll
        for (int c = 0; c < 2; ++c){
            const int n = n0 + c;
            const float bz = bzu_i[n], wy = Wzyu_i[n];
            float* zrow = szT + n*SROW + mbase;
#pragma unroll
            for (int rp = 0; rp < 4; ++rp){
                float2 v = unpack2(acc[rp][c]);
                const int m = mbase + 2*rp;
                zrow[2*rp]   = fmaxf(P * (v.x + bz + syy[m]   * wy), 0.f);
                zrow[2*rp+1] = fmaxf(P * (v.y + bz + syy[m+1] * wy), 0.f);
            }
        }

        // (c) unew = relu(PU*(u@Wu+bu))
        acc_zero(acc);
        gemmT(suT, Wu_i, acc, mbase, tcol);
        __syncthreads();          // all u reads done
#pragma unroll
        for (int c = 0; c < 2; ++c){
            const int n = n0 + c;
            const float bv = bu_i[n];
            float* urow = suT + n*SROW + mbase;
#pragma unroll
            for (int rp = 0; rp < 4; ++rp){
                float2 v = unpack2(acc[rp][c]);
                urow[2*rp]   = fmaxf(PU * (v.x + bv), 0.f);
                urow[2*rp+1] = fmaxf(PU * (v.y + bv), 0.f);
            }
        }
        __syncthreads();
    }

    // ---------------- final stage ----------------
    {
        const float* Wzuu2 = Wzuu + 2*H*H;
        const float* bzuu2 = bzuu + 2*H;
        const float* Wyuu2 = Wyuu + 2*H;

        ull acc[4][2];
        acc_zero(acc);
        gemmT(suT, Wzuu2, acc, mbase, tcol);
#pragma unroll
        for (int c = 0; c < 2; ++c){
            const int n = n0 + c;
            const float bz = bzuu2[n];
            float* zrow = szT + n*SROW + mbase;
#pragma unroll
            for (int rp = 0; rp < 4; ++rp){
                float2 v = unpack2(acc[rp][c]);
                zrow[2*rp]   *= fmaxf(PZU * (v.x + bz), 0.f);
                zrow[2*rp+1] *= fmaxf(PZU * (v.y + bz), 0.f);
            }
        }
        __syncthreads();

        // three K=512 dots per point (32 segments of 16)
        const int rrow = tid >> 5, rseg = tid & 31;
        float p1 = 0.f, p2 = 0.f, p3 = 0.f;
#pragma unroll 8
        for (int j = 0; j < 16; ++j){
            const int k = rseg + 32*j;
            const float uk = suT[k*SROW + rrow];
            const float zk = szT[k*SROW + rrow];
            p1 += zk * Wzzu_last[k];
            p2 += uk * Wzu_last[k];
            p3 += uk * Wyuu2[k];
        }
        const int ridx = rseg * 32 + rrow;
        sred[ridx]          = p1;
        sred[NT + ridx]     = p2;
        sred[2*NT + ridx]   = p3;
        __syncthreads();

        if (tid < MT && (m0 + tid) < Npts){
            float s1 = 0.f, s2 = 0.f, s3 = 0.f;
#pragma unroll
            for (int sgi = 0; sgi < 32; ++sgi){
                s1 += sred[sgi*32 + tid];
                s2 += sred[NT + sgi*32 + tid];
                s3 += sred[2*NT + sgi*32 + tid];
            }
            out[m0 + tid] = s1 + s2 + bzu_last[0]
                          + sc[tid*4+3] * (s3 + byuu[2]) * Wzyu_last[0];
        }
    }
}

extern "C" void kernel_launch(void* const* d_in, const int* in_sizes, int n_in,
                              void* d_out, int out_size)
{
    const float* coords    = (const float*)d_in[0];
    const float* Wu0       = (const float*)d_in[1];
    const float* bu0       = (const float*)d_in[2];
    const float* Wu        = (const float*)d_in[3];
    const float* bu        = (const float*)d_in[4];
    const float* Wzuu      = (const float*)d_in[5];
    const float* bzuu      = (const float*)d_in[6];
    const float* Wzzu      = (const float*)d_in[7];
    const float* Wzzu_last = (const float*)d_in[8];
    const float* Wyuu0     = (const float*)d_in[9];
    const float* byuu0     = (const float*)d_in[10];
    const float* Wyuu      = (const float*)d_in[11];
    const float* byuu      = (const float*)d_in[12];
    const float* Wzyu      = (const float*)d_in[13];
    const float* Wzyu_last = (const float*)d_in[14];
    const float* Wzu0      = (const float*)d_in[15];
    const float* bzu0      = (const float*)d_in[16];
    const float* Wzu       = (const float*)d_in[17];
    const float* bzu       = (const float*)d_in[18];
    const float* Wzu_last  = (const float*)d_in[19];
    const float* bzu_last  = (const float*)d_in[20];
    const float* pp        = (const float*)d_in[21];
    const float* ppu       = (const float*)d_in[22];
    const float* ppzu      = (const float*)d_in[23];
    float* out = (float*)d_out;

    const int N = in_sizes[0] / 4;          // coords is (N,4)
    const int grid = (N + MT - 1) / MT;
    const size_t smem_bytes = (size_t)(2*H*SROW + MT*4 + MT + 3*NT) * sizeof(float);

    cudaFuncSetAttribute(fcblock_kernel,
                         cudaFuncAttributeMaxDynamicSharedMemorySize,
                         (int)smem_bytes);

    fcblock_kernel<<<grid, NT, smem_bytes>>>(
        coords, Wu0, bu0, Wu, bu, Wzuu, bzuu, Wzzu, Wzzu_last,
        Wyuu0, byuu0, Wyuu, byuu, Wzyu, Wzyu_last,
        Wzu0, bzu0, Wzu, bzu, Wzu_last, bzu_last,
        pp, ppu, ppzu, out, N);
}

// round 13
// speedup vs baseline: 2.5643x; 2.5608x over previous
#include <cuda_runtime.h>
#include <cuda_bf16.h>
#include <cstdint>

#define H   512
#define MT  32
#define NT  512
#define KPB 1040                 // A row stride in bytes (520 bf16)

#define SM_SC    64
#define SM_SYY   576
#define SM_SRED  704
#define SM_A     8192
#define SM_TOTAL (8192 + 128*KPB)   // 141312

// B fragments: [g=9][ks=32][nt=64][h=2][t=32][2 x uint32]  -> 1 MB per gemm
static __device__ __align__(16) unsigned char g_B[9u * 1048576u];

__device__ __forceinline__ uint32_t s2u(const void* p){
    uint32_t a;
    asm("{ .reg .u64 t; cvta.to.shared.u64 t, %1; cvt.u32.u64 %0, t; }" : "=r"(a) : "l"(p));
    return a;
}
__device__ __forceinline__ void ldmA(uint32_t a[4], uint32_t addr){
    asm volatile("ldmatrix.sync.aligned.m8n8.x4.shared.b16 {%0,%1,%2,%3}, [%4];"
        : "=r"(a[0]), "=r"(a[1]), "=r"(a[2]), "=r"(a[3]) : "r"(addr));
}
__device__ __forceinline__ void mmabf(float d[4], const uint32_t a[4], uint32_t b0, uint32_t b1){
    asm volatile("mma.sync.aligned.m16n8k16.row.col.f32.bf16.bf16.f32 "
        "{%0,%1,%2,%3}, {%4,%5,%6,%7}, {%8,%9}, {%0,%1,%2,%3};"
        : "+f"(d[0]), "+f"(d[1]), "+f"(d[2]), "+f"(d[3])
        : "r"(a[0]), "r"(a[1]), "r"(a[2]), "r"(a[3]), "r"(b0), "r"(b1));
}
// A tile accessors (linear row-major, hi at row, lo at row+32)
__device__ __forceinline__ void putsplit(unsigned char* A, int row, int k, float v){
    __nv_bfloat16 h = __float2bfloat16(v);
    *(__nv_bfloat16*)(A + row*KPB + k*2)        = h;
    *(__nv_bfloat16*)(A + (row+32)*KPB + k*2)   = __float2bfloat16(v - __bfloat162float(h));
}
__device__ __forceinline__ float getf(const unsigned char* A, int row, int k){
    return __bfloat162float(*(const __nv_bfloat16*)(A + row*KPB + k*2))
         + __bfloat162float(*(const __nv_bfloat16*)(A + (row+32)*KPB + k*2));
}

// ---- weight prep: W[k][n] fp32 -> hi/lo bf16 fragment pairs ----
extern "C" __global__ void __launch_bounds__(256)
fc_conv(const float* __restrict__ Wzuu, const float* __restrict__ Wzzu,
        const float* __restrict__ Wzu,  const float* __restrict__ Wu)
{
    uint32_t idx = blockIdx.x * 256u + threadIdx.x;
    if (idx >= 9u * 32u * 64u * 32u * 2u) return;     // 1,179,648
    uint32_t reg = idx & 1u;
    uint32_t t   = (idx >> 1) & 31u;
    uint32_t nt  = (idx >> 6) & 63u;
    uint32_t ks  = (idx >> 12) & 31u;
    uint32_t g   = idx >> 17;

    const float* src;
    switch (g){
        case 0: src = Wzuu;           break;
        case 1: src = Wzzu;           break;
        case 2: src = Wzu;            break;
        case 3: src = Wu;             break;
        case 4: src = Wzuu + 262144;  break;
        case 5: src = Wzzu + 262144;  break;
        case 6: src = Wzu  + 262144;  break;
        case 7: src = Wu   + 262144;  break;
        default: src = Wzuu + 524288; break;
    }
    const uint32_t n  = nt * 8 + (t >> 2);
    const uint32_t k0 = ks * 16 + (t & 3) * 2 + reg * 8;
    const float w0 = src[k0 * H + n];
    const float w1 = src[(k0 + 1) * H + n];

    __nv_bfloat16 h0 = __float2bfloat16(w0), h1 = __float2bfloat16(w1);
    __nv_bfloat16 l0 = __float2bfloat16(w0 - __bfloat162float(h0));
    __nv_bfloat16 l1 = __float2bfloat16(w1 - __bfloat162float(h1));
    uint32_t hp = ((uint32_t)*(uint16_t*)&h1 << 16) | *(uint16_t*)&h0;
    uint32_t lp = ((uint32_t)*(uint16_t*)&l1 << 16) | *(uint16_t*)&l0;

    const uint32_t off = (((((g * 32u + ks) * 64u + nt) * 2u + 0u) * 32u + t) * 2u + reg) * 4u;
    *(uint32_t*)(g_B + off)        = hp;
    *(uint32_t*)(g_B + off + 256u) = lp;
}

// ---- main fused kernel ----
extern "C" __global__ void __launch_bounds__(NT, 1)
fc_main(const float* __restrict__ coords,
        const float* __restrict__ Wu0,  const float* __restrict__ bu0,
        const float* __restrict__ bu,   const float* __restrict__ bzuu,
        const float* __restrict__ Wyuu0,const float* __restrict__ byuu0,
        const float* __restrict__ Wyuu, const float* __restrict__ byuu,
        const float* __restrict__ Wzyu, const float* __restrict__ Wzyu_last,
        const float* __restrict__ Wzu0, const float* __restrict__ bzu0,
        const float* __restrict__ bzu,  const float* __restrict__ Wzzu_last,
        const float* __restrict__ Wzu_last, const float* __restrict__ bzu_last,
        const float* __restrict__ pp, const float* __restrict__ ppu,
        const float* __restrict__ ppzu,
        float* __restrict__ out, int Npts)
{
    extern __shared__ __align__(16) unsigned char smem[];
    float* sc   = (float*)(smem + SM_SC);
    float* syy  = (float*)(smem + SM_SYY);
    float* sred = (float*)(smem + SM_SRED);
    unsigned char* A = smem + SM_A;
    const uint32_t sbA = s2u(smem) + SM_A;

    const int tid = threadIdx.x, wid = tid >> 5, lane = tid & 31;
    const int m0 = blockIdx.x * MT;
    const float P = 10.f * pp[0], PU = 10.f * ppu[0], PZU = 10.f * ppzu[0];

    if (tid < 128){
        int gi = m0 * 4 + tid;
        sc[tid] = (gi < Npts * 4) ? coords[gi] : 0.f;
    }
    __syncthreads();

    // stage 0: A bands (u hi/lo rows 0/32, z hi/lo rows 64/96)
    {
        const int m = tid & 31, c0 = (tid >> 5) * 32;
        const float a0 = sc[m*4], a1 = sc[m*4+1], a2 = sc[m*4+2], y = sc[m*4+3];
        const float ys = y * (a0*Wyuu0[0] + a1*Wyuu0[1] + a2*Wyuu0[2] + byuu0[0]);
        for (int n = c0; n < c0 + 32; ++n){
            float zv = fmaxf(P *(a0*Wzu0[n] + a1*Wzu0[H+n] + a2*Wzu0[2*H+n] + bzu0[n] + ys*Wzyu[n]), 0.f);
            float uv = fmaxf(PU*(a0*Wu0[n]  + a1*Wu0[H+n]  + a2*Wu0[2*H+n]  + bu0[n]), 0.f);
            putsplit(A, m, n, uv);
            putsplit(A, 64 + m, n, zv);
        }
    }
    __syncthreads();

    const signed char tp[9] = {0, 1, 2, 3, 0, 1, 2, 3, 4};

    for (int s = 0; s < 9; ++s){
        const int type = tp[s];
        const int st = (s < 4) ? 0 : ((s < 8) ? 1 : 2);
        const int abase = (type == 1) ? 64 : 0;
        const unsigned char* gB = g_B + (size_t)s * 1048576u;

        float acc[2][4][4];
#pragma unroll
        for (int m = 0; m < 2; ++m)
#pragma unroll
            for (int j = 0; j < 4; ++j)
#pragma unroll
                for (int e = 0; e < 4; ++e) acc[m][j][e] = 0.f;

        uint2 bh[4], bl[4];
#pragma unroll
        for (int j = 0; j < 4; ++j){
            const unsigned char* p = gB + ((((size_t)0 * 64u + wid*4u + j) * 2u) * 32u + lane) * 8u;
            bh[j] = *(const uint2*)p;
            bl[j] = *(const uint2*)(p + 256u);
        }

#pragma unroll 2
        for (int ks = 0; ks < 32; ++ks){
            uint2 nbh[4], nbl[4];
            if (ks < 31){
#pragma unroll
                for (int j = 0; j < 4; ++j){
                    const unsigned char* p = gB + ((((size_t)(ks+1) * 64u + wid*4u + j) * 2u) * 32u + lane) * 8u;
                    nbh[j] = *(const uint2*)p;
                    nbl[j] = *(const uint2*)(p + 256u);
                }
            }
            uint32_t Ah0[4], Ah1[4], Al0[4], Al1[4];
            const uint32_t colb = (uint32_t)(ks * 32 + (lane >> 4) * 16);
            const uint32_t rsel = (uint32_t)(lane & 15);
            ldmA(Ah0, sbA + (abase      + rsel) * KPB + colb);
            ldmA(Ah1, sbA + (abase + 16 + rsel) * KPB + colb);
            ldmA(Al0, sbA + (abase + 32 + rsel) * KPB + colb);
            ldmA(Al1, sbA + (abase + 48 + rsel) * KPB + colb);
#pragma unroll
            for (int j = 0; j < 4; ++j){
                mmabf(acc[0][j], Ah0, bh[j].x, bh[j].y);
                mmabf(acc[1][j], Ah1, bh[j].x, bh[j].y);
                mmabf(acc[0][j], Al0, bh[j].x, bh[j].y);
                mmabf(acc[1][j], Al1, bh[j].x, bh[j].y);
                mmabf(acc[0][j], Ah0, bl[j].x, bl[j].y);
                mmabf(acc[1][j], Ah1, bl[j].x, bl[j].y);
            }
#pragma unroll
            for (int j = 0; j < 4; ++j){ bh[j] = nbh[j]; bl[j] = nbl[j]; }
        }
        __syncthreads();    // all warps finished reading A

        // in-register epilogue: thread owns rows {r0,r0+8}+16m, cols wid*32+j*8+(lane&3)*2+{0,1}
        const int r0 = lane >> 2, cb = (lane & 3) * 2;
#pragma unroll
        for (int m = 0; m < 2; ++m){
#pragma unroll
            for (int j = 0; j < 4; ++j){
#pragma unroll
                for (int e = 0; e < 4; ++e){
                    const int row = m*16 + r0 + (e >> 1) * 8;
                    const int n   = wid*32 + j*8 + cb + (e & 1);
                    const float d = acc[m][j][e];
                    if (type == 0 || type == 4){
                        float gt = fmaxf(PZU * (d + bzuu[st*H + n]), 0.f);
                        putsplit(A, 64 + row, n, getf(A, 64 + row, n) * gt);
                    } else if (type == 1){
                        putsplit(A, 64 + row, n, d);                    // stash zz@Wzzu
                    } else if (type == 2){
                        float t2 = d + bzu[st*H + n] + getf(A, 64 + row, n)
                                 + syy[row] * Wzyu[(st + 1)*H + n];
                        putsplit(A, 64 + row, n, fmaxf(P * t2, 0.f));
                    } else {
                        putsplit(A, row, n, fmaxf(PU * (d + bu[st*H + n]), 0.f));
                    }
                }
            }
        }
        if (type == 0){      // y-term partial dot over (unchanged) u
            const int seg = tid & 15, mm = tid >> 4;
            float ps = 0.f;
#pragma unroll 8
            for (int jj = 0; jj < 32; ++jj){
                const int k = seg + 16*jj;
                ps += getf(A, mm, k) * Wyuu[st*H + k];
            }
            sred[seg*32 + mm] = ps;
        }
        __syncthreads();
        if (type == 0 && tid < 32){
            float ssum = 0.f;
#pragma unroll
            for (int sg = 0; sg < 16; ++sg) ssum += sred[sg*32 + tid];
            syy[tid] = sc[tid*4 + 3] * (ssum + byuu[st]);
        }
        __syncthreads();
    }

    // final dots: p1 = zz.Wzzu_last, p2 = u.Wzu_last, p3 = u.Wyuu[2]
    {
        const int seg = tid & 15, mm = tid >> 4;
        float p1 = 0.f, p2 = 0.f, p3 = 0.f;
#pragma unroll 8
        for (int jj = 0; jj < 32; ++jj){
            const int k = seg + 16*jj;
            const float uk = getf(A, mm, k), zk = getf(A, 64 + mm, k);
            p1 += zk * Wzzu_last[k];
            p2 += uk * Wzu_last[k];
            p3 += uk * Wyuu[2*H + k];
        }
        sred[seg*32 + mm]        = p1;
        sred[512 + seg*32 + mm]  = p2;
        sred[1024 + seg*32 + mm] = p3;
        __syncthreads();
        if (tid < 32 && m0 + tid < Npts){
            float s1 = 0.f, s2 = 0.f, s3 = 0.f;
#pragma unroll
            for (int sg = 0; sg < 16; ++sg){
                s1 += sred[sg*32 + tid];
                s2 += sred[512 + sg*32 + tid];
                s3 += sred[1024 + sg*32 + tid];
            }
            out[m0 + tid] = s1 + s2 + bzu_last[0]
                          + sc[tid*4 + 3] * (s3 + byuu[2]) * Wzyu_last[0];
        }
    }
}

extern "C" void kernel_launch(void* const* d_in, const int* in_sizes, int n_in,
                              void* d_out, int out_size)
{
    const float* coords    = (const float*)d_in[0];
    const float* Wu0       = (const float*)d_in[1];
    const float* bu0       = (const float*)d_in[2];
    const float* Wu        = (const float*)d_in[3];
    const float* bu        = (const float*)d_in[4];
    const float* Wzuu      = (const float*)d_in[5];
    const float* bzuu      = (const float*)d_in[6];
    const float* Wzzu      = (const float*)d_in[7];
    const float* Wzzu_last = (const float*)d_in[8];
    const float* Wyuu0     = (const float*)d_in[9];
    const float* byuu0     = (const float*)d_in[10];
    const float* Wyuu      = (const float*)d_in[11];
    const float* byuu      = (const float*)d_in[12];
    const float* Wzyu      = (const float*)d_in[13];
    const float* Wzyu_last = (const float*)d_in[14];
    const float* Wzu0      = (const float*)d_in[15];
    const float* bzu0      = (const float*)d_in[16];
    const float* Wzu       = (const float*)d_in[17];
    const float* bzu       = (const float*)d_in[18];
    const float* Wzu_last  = (const float*)d_in[19];
    const float* bzu_last  = (const float*)d_in[20];
    const float* pp        = (const float*)d_in[21];
    const float* ppu       = (const float*)d_in[22];
    const float* ppzu      = (const float*)d_in[23];
    float* out = (float*)d_out;

    const int N = in_sizes[0] / 4;
    fc_conv<<<(9 * 131072 + 255) / 256, 256>>>(Wzuu, Wzzu, Wzu, Wu);

    cudaFuncSetAttribute(fc_main, cudaFuncAttributeMaxDynamicSharedMemorySize, SM_TOTAL);
    fc_main<<<(N + MT - 1) / MT, NT, SM_TOTAL>>>(
        coords, Wu0, bu0, bu, bzuu, Wyuu0, byuu0, Wyuu, byuu,
        Wzyu, Wzyu_last, Wzu0, bzu0, bzu, Wzzu_last, Wzu_last, bzu_last,
        pp, ppu, ppzu, out, N);
}

// round 15
// speedup vs baseline: 2.6090x; 1.0174x over previous
#include <cuda_runtime.h>
#include <cuda_bf16.h>
#include <cstdint>

#define H   512
#define MT  32
#define NT  512
#define KPB 1040                 // A row stride in bytes (520 bf16)

#define SM_SC    64
#define SM_SYY   576
#define SM_SRED  704
#define SM_A     8192
#define SM_TOTAL (8192 + 128*KPB)   // 141312

// B fragments: [g=9][ks=32][nt=64][h=2][t=32][2 x uint32]  -> 1 MB per gemm
static __device__ __align__(16) unsigned char g_B[9u * 1048576u];

__device__ __forceinline__ uint32_t s2u(const void* p){
    uint32_t a;
    asm("{ .reg .u64 t; cvta.to.shared.u64 t, %1; cvt.u32.u64 %0, t; }" : "=r"(a) : "l"(p));
    return a;
}
__device__ __forceinline__ void ldmA(uint32_t a[4], uint32_t addr){
    asm volatile("ldmatrix.sync.aligned.m8n8.x4.shared.b16 {%0,%1,%2,%3}, [%4];"
        : "=r"(a[0]), "=r"(a[1]), "=r"(a[2]), "=r"(a[3]) : "r"(addr));
}
__device__ __forceinline__ void mmabf(float d[4], const uint32_t a[4], uint32_t b0, uint32_t b1){
    asm volatile("mma.sync.aligned.m16n8k16.row.col.f32.bf16.bf16.f32 "
        "{%0,%1,%2,%3}, {%4,%5,%6,%7}, {%8,%9}, {%0,%1,%2,%3};"
        : "+f"(d[0]), "+f"(d[1]), "+f"(d[2]), "+f"(d[3])
        : "r"(a[0]), "r"(a[1]), "r"(a[2]), "r"(a[3]), "r"(b0), "r"(b1));
}
// A tile accessors (linear row-major, hi at row, lo at row+32)
__device__ __forceinline__ void putsplit(unsigned char* A, int row, int k, float v){
    __nv_bfloat16 h = __float2bfloat16(v);
    *(__nv_bfloat16*)(A + row*KPB + k*2)        = h;
    *(__nv_bfloat16*)(A + (row+32)*KPB + k*2)   = __float2bfloat16(v - __bfloat162float(h));
}
__device__ __forceinline__ float getf(const unsigned char* A, int row, int k){
    return __bfloat162float(*(const __nv_bfloat16*)(A + row*KPB + k*2))
         + __bfloat162float(*(const __nv_bfloat16*)(A + (row+32)*KPB + k*2));
}

// ---- weight prep: W[k][n] fp32 -> hi/lo bf16 fragment pairs ----
extern "C" __global__ void __launch_bounds__(256)
fc_conv(const float* __restrict__ Wzuu, const float* __restrict__ Wzzu,
        const float* __restrict__ Wzu,  const float* __restrict__ Wu)
{
    uint32_t idx = blockIdx.x * 256u + threadIdx.x;
    if (idx >= 9u * 32u * 64u * 32u * 2u) return;     // 1,179,648
    uint32_t reg = idx & 1u;
    uint32_t t   = (idx >> 1) & 31u;
    uint32_t nt  = (idx >> 6) & 63u;
    uint32_t ks  = (idx >> 12) & 31u;
    uint32_t g   = idx >> 17;

    const float* src;
    switch (g){
        case 0: src = Wzuu;           break;
        case 1: src = Wzzu;           break;
        case 2: src = Wzu;            break;
        case 3: src = Wu;             break;
        case 4: src = Wzuu + 262144;  break;
        case 5: src = Wzzu + 262144;  break;
        case 6: src = Wzu  + 262144;  break;
        case 7: src = Wu   + 262144;  break;
        default: src = Wzuu + 524288; break;
    }
    const uint32_t n  = nt * 8 + (t >> 2);
    const uint32_t k0 = ks * 16 + (t & 3) * 2 + reg * 8;
    const float w0 = src[k0 * H + n];
    const float w1 = src[(k0 + 1) * H + n];

    __nv_bfloat16 h0 = __float2bfloat16(w0), h1 = __float2bfloat16(w1);
    __nv_bfloat16 l0 = __float2bfloat16(w0 - __bfloat162float(h0));
    __nv_bfloat16 l1 = __float2bfloat16(w1 - __bfloat162float(h1));
    uint32_t hp = ((uint32_t)*(uint16_t*)&h1 << 16) | *(uint16_t*)&h0;
    uint32_t lp = ((uint32_t)*(uint16_t*)&l1 << 16) | *(uint16_t*)&l0;

    const uint32_t off = (((((g * 32u + ks) * 64u + nt) * 2u + 0u) * 32u + t) * 2u + reg) * 4u;
    *(uint32_t*)(g_B + off)        = hp;
    *(uint32_t*)(g_B + off + 256u) = lp;
}

// ---- one 32-k-step slab with depth-2 register prefetch (unroll-by-2) ----
__device__ __forceinline__ void sweep_slab(const unsigned char* __restrict__ gB,
                                           uint32_t sbA, int abase, int wid, int lane,
                                           float acc[2][4][4])
{
    const size_t wj = (size_t)(wid * 4);
    uint2 bh0[4], bl0[4], bh1[4], bl1[4];
#pragma unroll
    for (int j = 0; j < 4; ++j){
        const unsigned char* p0 = gB + ((((size_t)0*64u + wj + j)*2u)*32u + lane)*8u;
        const unsigned char* p1 = gB + ((((size_t)1*64u + wj + j)*2u)*32u + lane)*8u;
        bh0[j] = *(const uint2*)p0; bl0[j] = *(const uint2*)(p0 + 256u);
        bh1[j] = *(const uint2*)p1; bl1[j] = *(const uint2*)(p1 + 256u);
    }
    const uint32_t rsel  = (uint32_t)(lane & 15);
    const uint32_t chalf = (uint32_t)((lane >> 4) * 16);
    const uint32_t aoff  = sbA + (uint32_t)(abase + rsel) * KPB + chalf;

#pragma unroll 1
    for (int ks = 0; ks < 32; ks += 2){
        uint32_t Ah0[4], Ah1[4], Al0[4], Al1[4];
        uint32_t cb = (uint32_t)(ks * 32);
        ldmA(Ah0, aoff + cb);
        ldmA(Ah1, aoff + 16*KPB + cb);
        ldmA(Al0, aoff + 32*KPB + cb);
        ldmA(Al1, aoff + 48*KPB + cb);
#pragma unroll
        for (int j = 0; j < 4; ++j){
            mmabf(acc[0][j], Ah0, bh0[j].x, bh0[j].y);
            mmabf(acc[1][j], Ah1, bh0[j].x, bh0[j].y);
            mmabf(acc[0][j], Al0, bh0[j].x, bh0[j].y);
            mmabf(acc[1][j], Al1, bh0[j].x, bh0[j].y);
            mmabf(acc[0][j], Ah0, bl0[j].x, bl0[j].y);
            mmabf(acc[1][j], Ah1, bl0[j].x, bl0[j].y);
        }
        {   // refill set0 for ks+2 (distance ~2 k-steps covers L2 latency)
            const size_t kn = (size_t)((ks + 2) & 31);
#pragma unroll
            for (int j = 0; j < 4; ++j){
                const unsigned char* p = gB + (((kn*64u + wj + j)*2u)*32u + lane)*8u;
                bh0[j] = *(const uint2*)p; bl0[j] = *(const uint2*)(p + 256u);
            }
        }
        cb += 32;
        ldmA(Ah0, aoff + cb);
        ldmA(Ah1, aoff + 16*KPB + cb);
        ldmA(Al0, aoff + 32*KPB + cb);
        ldmA(Al1, aoff + 48*KPB + cb);
#pragma unroll
        for (int j = 0; j < 4; ++j){
            mmabf(acc[0][j], Ah0, bh1[j].x, bh1[j].y);
            mmabf(acc[1][j], Ah1, bh1[j].x, bh1[j].y);
            mmabf(acc[0][j], Al0, bh1[j].x, bh1[j].y);
            mmabf(acc[1][j], Al1, bh1[j].x, bh1[j].y);
            mmabf(acc[0][j], Ah0, bl1[j].x, bl1[j].y);
            mmabf(acc[1][j], Ah1, bl1[j].x, bl1[j].y);
        }
        {   // refill set1 for ks+3
            const size_t kn = (size_t)((ks + 3) & 31);
#pragma unroll
            for (int j = 0; j < 4; ++j){
                const unsigned char* p = gB + (((kn*64u + wj + j)*2u)*32u + lane)*8u;
                bh1[j] = *(const uint2*)p; bl1[j] = *(const uint2*)(p + 256u);
            }
        }
    }
}

// ---- main fused kernel ----
extern "C" __global__ void __launch_bounds__(NT, 1)
fc_main(const float* __restrict__ coords,
        const float* __restrict__ Wu0,  const float* __restrict__ bu0,
        const float* __restrict__ bu,   const float* __restrict__ bzuu,
        const float* __restrict__ Wyuu0,const float* __restrict__ byuu0,
        const float* __restrict__ Wyuu, const float* __restrict__ byuu,
        const float* __restrict__ Wzyu, const float* __restrict__ Wzyu_last,
        const float* __restrict__ Wzu0, const float* __restrict__ bzu0,
        const float* __restrict__ bzu,  const float* __restrict__ Wzzu_last,
        const float* __restrict__ Wzu_last, const float* __restrict__ bzu_last,
        const float* __restrict__ pp, const float* __restrict__ ppu,
        const float* __restrict__ ppzu,
        float* __restrict__ out, int Npts)
{
    extern __shared__ __align__(16) unsigned char smem[];
    float* sc   = (float*)(smem + SM_SC);
    float* syy  = (float*)(smem + SM_SYY);
    float* sred = (float*)(smem + SM_SRED);
    unsigned char* A = smem + SM_A;
    const uint32_t sbA = s2u(smem) + SM_A;

    const int tid = threadIdx.x, wid = tid >> 5, lane = tid & 31;
    const int m0 = blockIdx.x * MT;
    const float P = 10.f * pp[0], PU = 10.f * ppu[0], PZU = 10.f * ppzu[0];

    if (tid < 128){
        int gi = m0 * 4 + tid;
        sc[tid] = (gi < Npts * 4) ? coords[gi] : 0.f;
    }
    __syncthreads();

    // stage 0: A bands (u hi/lo rows 0/32, z hi/lo rows 64/96)
    {
        const int m = tid & 31, c0 = (tid >> 5) * 32;
        const float a0 = sc[m*4], a1 = sc[m*4+1], a2 = sc[m*4+2], y = sc[m*4+3];
        const float ys = y * (a0*Wyuu0[0] + a1*Wyuu0[1] + a2*Wyuu0[2] + byuu0[0]);
        for (int n = c0; n < c0 + 32; ++n){
            float zv = fmaxf(P *(a0*Wzu0[n] + a1*Wzu0[H+n] + a2*Wzu0[2*H+n] + bzu0[n] + ys*Wzyu[n]), 0.f);
            float uv = fmaxf(PU*(a0*Wu0[n]  + a1*Wu0[H+n]  + a2*Wu0[2*H+n]  + bu0[n]), 0.f);
            putsplit(A, m, n, uv);
            putsplit(A, 64 + m, n, zv);
        }
    }
    __syncthreads();

    // 7 sweeps: G(gate) / Z(z-update, 2 slabs) / U(u-update), x2 stages, + final gate
    const signed char sw_type[7] = {0, 2, 3, 0, 2, 3, 4};
    const signed char sw_g[7]    = {0, 1, 3, 4, 5, 7, 8};
    const signed char sw_st[7]   = {0, 0, 0, 1, 1, 1, 2};

    for (int s = 0; s < 7; ++s){
        const int type = sw_type[s];
        const int st   = sw_st[s];
        const unsigned char* gB = g_B + (size_t)sw_g[s] * 1048576u;

        float acc[2][4][4];
#pragma unroll
        for (int m = 0; m < 2; ++m)
#pragma unroll
            for (int j = 0; j < 4; ++j)
#pragma unroll
                for (int e = 0; e < 4; ++e) acc[m][j][e] = 0.f;

        if (type == 2){
            sweep_slab(gB,            sbA, 64, wid, lane, acc);   // zz @ Wzzu
            sweep_slab(gB + 1048576u, sbA, 0,  wid, lane, acc);   // + u @ Wzu
        } else {
            sweep_slab(gB, sbA, 0, wid, lane, acc);               // u @ W*
        }
        __syncthreads();    // all warps done reading A

        // in-register epilogue: thread owns rows {r0,r0+8}+16m, cols wid*32+j*8+(lane&3)*2+{0,1}
        const int r0 = lane >> 2, cb = (lane & 3) * 2;
#pragma unroll
        for (int m = 0; m < 2; ++m){
#pragma unroll
            for (int j = 0; j < 4; ++j){
#pragma unroll
                for (int e = 0; e < 4; ++e){
                    const int row = m*16 + r0 + (e >> 1) * 8;
                    const int n   = wid*32 + j*8 + cb + (e & 1);
                    const float d = acc[m][j][e];
                    if (type == 0 || type == 4){
                        float gt = fmaxf(PZU * (d + bzuu[st*H + n]), 0.f);
                        putsplit(A, 64 + row, n, getf(A, 64 + row, n) * gt);
                    } else if (type == 2){
                        float t2 = d + bzu[st*H + n] + syy[row] * Wzyu[(st + 1)*H + n];
                        putsplit(A, 64 + row, n, fmaxf(P * t2, 0.f));
                    } else {
                        putsplit(A, row, n, fmaxf(PU * (d + bu[st*H + n]), 0.f));
                    }
                }
            }
        }
        if (type == 0){      // y-term partial dot over (unchanged) u
            const int seg = tid & 15, mm = tid >> 4;
            float ps = 0.f;
#pragma unroll 8
            for (int jj = 0; jj < 32; ++jj){
                const int k = seg + 16*jj;
                ps += getf(A, mm, k) * Wyuu[st*H + k];
            }
            sred[seg*32 + mm] = ps;
        }
        __syncthreads();
        if (type == 0 && tid < 32){
            float ssum = 0.f;
#pragma unroll
            for (int sg = 0; sg < 16; ++sg) ssum += sred[sg*32 + tid];
            syy[tid] = sc[tid*4 + 3] * (ssum + byuu[st]);
        }
        __syncthreads();
    }

    // final dots: p1 = zz.Wzzu_last, p2 = u.Wzu_last, p3 = u.Wyuu[2]
    {
        const int seg = tid & 15, mm = tid >> 4;
        float p1 = 0.f, p2 = 0.f, p3 = 0.f;
#pragma unroll 8
        for (int jj = 0; jj < 32; ++jj){
            const int k = seg + 16*jj;
            const float uk = getf(A, mm, k), zk = getf(A, 64 + mm, k);
            p1 += zk * Wzzu_last[k];
            p2 += uk * Wzu_last[k];
            p3 += uk * Wyuu[2*H + k];
        }
        sred[seg*32 + mm]        = p1;
        sred[512 + seg*32 + mm]  = p2;
        sred[1024 + seg*32 + mm] = p3;
        __syncthreads();
        if (tid < 32 && m0 + tid < Npts){
            float s1 = 0.f, s2 = 0.f, s3 = 0.f;
#pragma unroll
            for (int sg = 0; sg < 16; ++sg){
                s1 += sred[sg*32 + tid];
                s2 += sred[512 + sg*32 + tid];
                s3 += sred[1024 + sg*32 + tid];
            }
            out[m0 + tid] = s1 + s2 + bzu_last[0]
                          + sc[tid*4 + 3] * (s3 + byuu[2]) * Wzyu_last[0];
        }
    }
}

extern "C" void kernel_launch(void* const* d_in, const int* in_sizes, int n_in,
                              void* d_out, int out_size)
{
    const float* coords    = (const float*)d_in[0];
    const float* Wu0       = (const float*)d_in[1];
    const float* bu0       = (const float*)d_in[2];
    const float* Wu        = (const float*)d_in[3];
    const float* bu        = (const float*)d_in[4];
    const float* Wzuu      = (const float*)d_in[5];
    const float* bzuu      = (const float*)d_in[6];
    const float* Wzzu      = (const float*)d_in[7];
    const float* Wzzu_last = (const float*)d_in[8];
    const float* Wyuu0     = (const float*)d_in[9];
    const float* byuu0     = (const float*)d_in[10];
    const float* Wyuu      = (const float*)d_in[11];
    const float* byuu      = (const float*)d_in[12];
    const float* Wzyu      = (const float*)d_in[13];
    const float* Wzyu_last = (const float*)d_in[14];
    const float* Wzu0      = (const float*)d_in[15];
    const float* bzu0      = (const float*)d_in[16];
    const float* Wzu       = (const float*)d_in[17];
    const float* bzu       = (const float*)d_in[18];
    const float* Wzu_last  = (const float*)d_in[19];
    const float* bzu_last  = (const float*)d_in[20];
    const float* pp        = (const float*)d_in[21];
    const float* ppu       = (const float*)d_in[22];
    const float* ppzu      = (const float*)d_in[23];
    float* out = (float*)d_out;

    const int N = in_sizes[0] / 4;
    fc_conv<<<(9 * 131072 + 255) / 256, 256>>>(Wzuu, Wzzu, Wzu, Wu);

    cudaFuncSetAttribute(fc_main, cudaFuncAttributeMaxDynamicSharedMemorySize, SM_TOTAL);
    fc_main<<<(N + MT - 1) / MT, NT, SM_TOTAL>>>(
        coords, Wu0, bu0, bu, bzuu, Wyuu0, byuu0, Wyuu, byuu,
        Wzyu, Wzyu_last, Wzu0, bzu0, bzu, Wzzu_last, Wzu_last, bzu_last,
        pp, ppu, ppzu, out, N);
}

// round 16
// speedup vs baseline: 2.6258x; 1.0064x over previous
#include <cuda_runtime.h>
#include <cuda_bf16.h>
#include <cstdint>

#define H   512
#define MT  32
#define NT  1024
#define KPB 1040                 // A row stride in bytes (520 bf16)

#define SM_SC    64
#define SM_SYY   576
#define SM_SRED  704
#define SM_A     13056
#define SM_TOTAL (13056 + 128*KPB)   // 146176

// B fragments: [g=9][ks=32][nt=64][h=2][t=32][2 x uint32]  -> 1 MB per gemm
static __device__ __align__(16) unsigned char g_B[9u * 1048576u];

__device__ __forceinline__ uint32_t s2u(const void* p){
    uint32_t a;
    asm("{ .reg .u64 t; cvta.to.shared.u64 t, %1; cvt.u32.u64 %0, t; }" : "=r"(a) : "l"(p));
    return a;
}
__device__ __forceinline__ void ldmA(uint32_t a[4], uint32_t addr){
    asm volatile("ldmatrix.sync.aligned.m8n8.x4.shared.b16 {%0,%1,%2,%3}, [%4];"
        : "=r"(a[0]), "=r"(a[1]), "=r"(a[2]), "=r"(a[3]) : "r"(addr));
}
__device__ __forceinline__ void mmabf(float d[4], const uint32_t a[4], uint32_t b0, uint32_t b1){
    asm volatile("mma.sync.aligned.m16n8k16.row.col.f32.bf16.bf16.f32 "
        "{%0,%1,%2,%3}, {%4,%5,%6,%7}, {%8,%9}, {%0,%1,%2,%3};"
        : "+f"(d[0]), "+f"(d[1]), "+f"(d[2]), "+f"(d[3])
        : "r"(a[0]), "r"(a[1]), "r"(a[2]), "r"(a[3]), "r"(b0), "r"(b1));
}
// A tile accessors (linear row-major, hi at row, lo at row+32)
__device__ __forceinline__ void putsplit(unsigned char* A, int row, int k, float v){
    __nv_bfloat16 h = __float2bfloat16(v);
    *(__nv_bfloat16*)(A + row*KPB + k*2)        = h;
    *(__nv_bfloat16*)(A + (row+32)*KPB + k*2)   = __float2bfloat16(v - __bfloat162float(h));
}
__device__ __forceinline__ float getf(const unsigned char* A, int row, int k){
    return __bfloat162float(*(const __nv_bfloat16*)(A + row*KPB + k*2))
         + __bfloat162float(*(const __nv_bfloat16*)(A + (row+32)*KPB + k*2));
}

// ---- weight prep: W[k][n] fp32 -> hi/lo bf16 fragment pairs ----
extern "C" __global__ void __launch_bounds__(256)
fc_conv(const float* __restrict__ Wzuu, const float* __restrict__ Wzzu,
        const float* __restrict__ Wzu,  const float* __restrict__ Wu)
{
    uint32_t idx = blockIdx.x * 256u + threadIdx.x;
    if (idx >= 9u * 32u * 64u * 32u * 2u) return;     // 1,179,648
    uint32_t reg = idx & 1u;
    uint32_t t   = (idx >> 1) & 31u;
    uint32_t nt  = (idx >> 6) & 63u;
    uint32_t ks  = (idx >> 12) & 31u;
    uint32_t g   = idx >> 17;

    const float* src;
    switch (g){
        case 0: src = Wzuu;           break;
        case 1: src = Wzzu;           break;
        case 2: src = Wzu;            break;
        case 3: src = Wu;             break;
        case 4: src = Wzuu + 262144;  break;
        case 5: src = Wzzu + 262144;  break;
        case 6: src = Wzu  + 262144;  break;
        case 7: src = Wu   + 262144;  break;
        default: src = Wzuu + 524288; break;
    }
    const uint32_t n  = nt * 8 + (t >> 2);
    const uint32_t k0 = ks * 16 + (t & 3) * 2 + reg * 8;
    const float w0 = src[k0 * H + n];
    const float w1 = src[(k0 + 1) * H + n];

    __nv_bfloat16 h0 = __float2bfloat16(w0), h1 = __float2bfloat16(w1);
    __nv_bfloat16 l0 = __float2bfloat16(w0 - __bfloat162float(h0));
    __nv_bfloat16 l1 = __float2bfloat16(w1 - __bfloat162float(h1));
    uint32_t hp = ((uint32_t)*(uint16_t*)&h1 << 16) | *(uint16_t*)&h0;
    uint32_t lp = ((uint32_t)*(uint16_t*)&l1 << 16) | *(uint16_t*)&l0;

    const uint32_t off = (((((g * 32u + ks) * 64u + nt) * 2u + 0u) * 32u + t) * 2u + reg) * 4u;
    *(uint32_t*)(g_B + off)        = hp;
    *(uint32_t*)(g_B + off + 256u) = lp;
}

// ---- one 32-k-step slab; 2 n-tiles per warp; depth-1 register prefetch ----
// (a k-step is ~700+ cyc CTA-wide, >> L2 latency, so depth-1 suffices)
__device__ __forceinline__ void sweep_slab(const unsigned char* __restrict__ gB,
                                           uint32_t sbA, int abase, int wid, int lane,
                                           float acc[2][2][4])
{
    const size_t wj = (size_t)(wid * 2);
    uint2 bh[2], bl[2];
#pragma unroll
    for (int j = 0; j < 2; ++j){
        const unsigned char* p = gB + ((((size_t)0*64u + wj + j)*2u)*32u + lane)*8u;
        bh[j] = *(const uint2*)p; bl[j] = *(const uint2*)(p + 256u);
    }
    const uint32_t rsel  = (uint32_t)(lane & 15);
    const uint32_t chalf = (uint32_t)((lane >> 4) * 16);
    const uint32_t aoff  = sbA + (uint32_t)(abase + rsel) * KPB + chalf;

#pragma unroll 2
    for (int ks = 0; ks < 32; ++ks){
        uint32_t Ah0[4], Ah1[4], Al0[4], Al1[4];
        const uint32_t cb = (uint32_t)(ks * 32);
        ldmA(Ah0, aoff + cb);
        ldmA(Ah1, aoff + 16*KPB + cb);
        ldmA(Al0, aoff + 32*KPB + cb);
        ldmA(Al1, aoff + 48*KPB + cb);
        uint2 nbh[2], nbl[2];
        {
            const size_t kn = (size_t)((ks + 1) & 31);
#pragma unroll
            for (int j = 0; j < 2; ++j){
                const unsigned char* p = gB + (((kn*64u + wj + j)*2u)*32u + lane)*8u;
                nbh[j] = *(const uint2*)p; nbl[j] = *(const uint2*)(p + 256u);
            }
        }
#pragma unroll
        for (int j = 0; j < 2; ++j){
            mmabf(acc[0][j], Ah0, bh[j].x, bh[j].y);
            mmabf(acc[1][j], Ah1, bh[j].x, bh[j].y);
            mmabf(acc[0][j], Al0, bh[j].x, bh[j].y);
            mmabf(acc[1][j], Al1, bh[j].x, bh[j].y);
            mmabf(acc[0][j], Ah0, bl[j].x, bl[j].y);
            mmabf(acc[1][j], Ah1, bl[j].x, bl[j].y);
        }
#pragma unroll
        for (int j = 0; j < 2; ++j){ bh[j] = nbh[j]; bl[j] = nbl[j]; }
    }
}

// ---- main fused kernel ----
extern "C" __global__ void __launch_bounds__(NT, 1)
fc_main(const float* __restrict__ coords,
        const float* __restrict__ Wu0,  const float* __restrict__ bu0,
        const float* __restrict__ bu,   const float* __restrict__ bzuu,
        const float* __restrict__ Wyuu0,const float* __restrict__ byuu0,
        const float* __restrict__ Wyuu, const float* __restrict__ byuu,
        const float* __restrict__ Wzyu, const float* __restrict__ Wzyu_last,
        const float* __restrict__ Wzu0, const float* __restrict__ bzu0,
        const float* __restrict__ bzu,  const float* __restrict__ Wzzu_last,
        const float* __restrict__ Wzu_last, const float* __restrict__ bzu_last,
        const float* __restrict__ pp, const float* __restrict__ ppu,
        const float* __restrict__ ppzu,
        float* __restrict__ out, int Npts)
{
    extern __shared__ __align__(16) unsigned char smem[];
    float* sc   = (float*)(smem + SM_SC);
    float* syy  = (float*)(smem + SM_SYY);
    float* sred = (float*)(smem + SM_SRED);
    unsigned char* A = smem + SM_A;
    const uint32_t sbA = s2u(smem) + SM_A;

    const int tid = threadIdx.x, wid = tid >> 5, lane = tid & 31;
    const int m0 = blockIdx.x * MT;
    const float P = 10.f * pp[0], PU = 10.f * ppu[0], PZU = 10.f * ppzu[0];

    if (tid < 128){
        int gi = m0 * 4 + tid;
        sc[tid] = (gi < Npts * 4) ? coords[gi] : 0.f;
    }
    __syncthreads();

    // stage 0: A bands (u hi/lo rows 0/32, z hi/lo rows 64/96)
    {
        const int m = tid & 31, c0 = (tid >> 5) * 16;
        const float a0 = sc[m*4], a1 = sc[m*4+1], a2 = sc[m*4+2], y = sc[m*4+3];
        const float ys = y * (a0*Wyuu0[0] + a1*Wyuu0[1] + a2*Wyuu0[2] + byuu0[0]);
        for (int n = c0; n < c0 + 16; ++n){
            float zv = fmaxf(P *(a0*Wzu0[n] + a1*Wzu0[H+n] + a2*Wzu0[2*H+n] + bzu0[n] + ys*Wzyu[n]), 0.f);
            float uv = fmaxf(PU*(a0*Wu0[n]  + a1*Wu0[H+n]  + a2*Wu0[2*H+n]  + bu0[n]), 0.f);
            putsplit(A, m, n, uv);
            putsplit(A, 64 + m, n, zv);
        }
    }
    __syncthreads();

    // 7 sweeps: G(gate) / Z(z-update, 2 slabs) / U(u-update), x2 stages, + final gate
    const signed char sw_type[7] = {0, 2, 3, 0, 2, 3, 4};
    const signed char sw_g[7]    = {0, 1, 3, 4, 5, 7, 8};
    const signed char sw_st[7]   = {0, 0, 0, 1, 1, 1, 2};

    for (int s = 0; s < 7; ++s){
        const int type = sw_type[s];
        const int st   = sw_st[s];
        const unsigned char* gB = g_B + (size_t)sw_g[s] * 1048576u;

        float acc[2][2][4];
#pragma unroll
        for (int m = 0; m < 2; ++m)
#pragma unroll
            for (int j = 0; j < 2; ++j)
#pragma unroll
                for (int e = 0; e < 4; ++e) acc[m][j][e] = 0.f;

        if (type == 2){
            sweep_slab(gB,            sbA, 64, wid, lane, acc);   // zz @ Wzzu
            sweep_slab(gB + 1048576u, sbA, 0,  wid, lane, acc);   // + u @ Wzu
        } else {
            sweep_slab(gB, sbA, 0, wid, lane, acc);               // u @ W*
        }
        __syncthreads();    // all warps done reading A

        // in-register epilogue: thread owns rows {r0,r0+8}+16m, cols wid*16+j*8+(lane&3)*2+{0,1}
        const int r0 = lane >> 2, cb = (lane & 3) * 2;
#pragma unroll
        for (int m = 0; m < 2; ++m){
#pragma unroll
            for (int j = 0; j < 2; ++j){
#pragma unroll
                for (int e = 0; e < 4; ++e){
                    const int row = m*16 + r0 + (e >> 1) * 8;
                    const int n   = wid*16 + j*8 + cb + (e & 1);
                    const float d = acc[m][j][e];
                    if (type == 0 || type == 4){
                        float gt = fmaxf(PZU * (d + bzuu[st*H + n]), 0.f);
                        putsplit(A, 64 + row, n, getf(A, 64 + row, n) * gt);
                    } else if (type == 2){
                        float t2 = d + bzu[st*H + n] + syy[row] * Wzyu[(st + 1)*H + n];
                        putsplit(A, 64 + row, n, fmaxf(P * t2, 0.f));
                    } else {
                        putsplit(A, row, n, fmaxf(PU * (d + bu[st*H + n]), 0.f));
                    }
                }
            }
        }
        if (type == 0){      // y-term partial dot over (unchanged) u
            const int seg = tid & 31, mm = tid >> 5;
            float ps = 0.f;
#pragma unroll 8
            for (int jj = 0; jj < 16; ++jj){
                const int k = seg + 32*jj;
                ps += getf(A, mm, k) * Wyuu[st*H + k];
            }
            sred[seg*32 + mm] = ps;
        }
        __syncthreads();
        if (type == 0 && tid < 32){
            float ssum = 0.f;
#pragma unroll
            for (int sg = 0; sg < 32; ++sg) ssum += sred[sg*32 + tid];
            syy[tid] = sc[tid*4 + 3] * (ssum + byuu[st]);
        }
        __syncthreads();
    }

    // final dots: p1 = zz.Wzzu_last, p2 = u.Wzu_last, p3 = u.Wyuu[2]
    {
        const int seg = tid & 31, mm = tid >> 5;
        float p1 = 0.f, p2 = 0.f, p3 = 0.f;
#pragma unroll 8
        for (int jj = 0; jj < 16; ++jj){
            const int k = seg + 32*jj;
            const float uk = getf(A, mm, k), zk = getf(A, 64 + mm, k);
            p1 += zk * Wzzu_last[k];
            p2 += uk * Wzu_last[k];
            p3 += uk * Wyuu[2*H + k];
        }
        sred[seg*32 + mm]         = p1;
        sred[1024 + seg*32 + mm]  = p2;
        sred[2048 + seg*32 + mm]  = p3;
        __syncthreads();
        if (tid < 32 && m0 + tid < Npts){
            float s1 = 0.f, s2 = 0.f, s3 = 0.f;
#pragma unroll
            for (int sg = 0; sg < 32; ++sg){
                s1 += sred[sg*32 + tid];
                s2 += sred[1024 + sg*32 + tid];
                s3 += sred[2048 + sg*32 + tid];
            }
            out[m0 + tid] = s1 + s2 + bzu_last[0]
                          + sc[tid*4 + 3] * (s3 + byuu[2]) * Wzyu_last[0];
        }
    }
}

extern "C" void kernel_launch(void* const* d_in, const int* in_sizes, int n_in,
                              void* d_out, int out_size)
{
    const float* coords    = (const float*)d_in[0];
    const float* Wu0       = (const float*)d_in[1];
    const float* bu0       = (const float*)d_in[2];
    const float* Wu        = (const float*)d_in[3];
    const float* bu        = (const float*)d_in[4];
    const float* Wzuu      = (const float*)d_in[5];
    const float* bzuu      = (const float*)d_in[6];
    const float* Wzzu      = (const float*)d_in[7];
    const float* Wzzu_last = (const float*)d_in[8];
    const float* Wyuu0     = (const float*)d_in[9];
    const float* byuu0     = (const float*)d_in[10];
    const float* Wyuu      = (const float*)d_in[11];
    const float* byuu      = (const float*)d_in[12];
    const float* Wzyu      = (const float*)d_in[13];
    const float* Wzyu_last = (const float*)d_in[14];
    const float* Wzu0      = (const float*)d_in[15];
    const float* bzu0      = (const float*)d_in[16];
    const float* Wzu       = (const float*)d_in[17];
    const float* bzu       = (const float*)d_in[18];
    const float* Wzu_last  = (const float*)d_in[19];
    const float* bzu_last  = (const float*)d_in[20];
    const float* pp        = (const float*)d_in[21];
    const float* ppu       = (const float*)d_in[22];
    const float* ppzu      = (const float*)d_in[23];
    float* out = (float*)d_out;

    const int N = in_sizes[0] / 4;
    fc_conv<<<(9 * 131072 + 255) / 256, 256>>>(Wzuu, Wzzu, Wzu, Wu);

    cudaFuncSetAttribute(fc_main, cudaFuncAttributeMaxDynamicSharedMemorySize, SM_TOTAL);
    fc_main<<<(N + MT - 1) / MT, NT, SM_TOTAL>>>(
        coords, Wu0, bu0, bu, bzuu, Wyuu0, byuu0, Wyuu, byuu,
        Wzyu, Wzyu_last, Wzu0, bzu0, bzu, Wzzu_last, Wzu_last, bzu_last,
        pp, ppu, ppzu, out, N);
}

// round 17
// speedup vs baseline: 3.0938x; 1.1782x over previous
#include <cuda_runtime.h>
#include <cuda_bf16.h>
#include <cstdint>

#define H   512
#define MT  32
#define NT  1024
#define KPB 1040                 // A row stride in bytes (520 bf16)

#define SM_SC    64
#define SM_SYY   576
#define SM_SRED  704
#define SM_A     13056
#define SM_TOTAL (13056 + 128*KPB)   // 146176

// B fragments: [g=9][ks=32][w=32][hi 512B | lo 512B] -> 1 MB per gemm.
// Within hi/lo: lane t's 16 B = {j0.reg0, j0.reg1, j1.reg0, j1.reg1} ->
// one LDG.128 per lane fetches BOTH n-tile fragments for that half.
// +32 KB pad: the wrap-prefetch at ks=31 of the last gemm reads past the
// 9 MB of real data (values unused).
static __device__ __align__(16) unsigned char g_B[9u * 1048576u + 32768u];

__device__ __forceinline__ uint32_t s2u(const void* p){
    uint32_t a;
    asm("{ .reg .u64 t; cvta.to.shared.u64 t, %1; cvt.u32.u64 %0, t; }" : "=r"(a) : "l"(p));
    return a;
}
__device__ __forceinline__ void ldmA(uint32_t a[4], uint32_t addr){
    asm volatile("ldmatrix.sync.aligned.m8n8.x4.shared.b16 {%0,%1,%2,%3}, [%4];"
        : "=r"(a[0]), "=r"(a[1]), "=r"(a[2]), "=r"(a[3]) : "r"(addr));
}
__device__ __forceinline__ void mmabf(float d[4], const uint32_t a[4], uint32_t b0, uint32_t b1){
    asm volatile("mma.sync.aligned.m16n8k16.row.col.f32.bf16.bf16.f32 "
        "{%0,%1,%2,%3}, {%4,%5,%6,%7}, {%8,%9}, {%0,%1,%2,%3};"
        : "+f"(d[0]), "+f"(d[1]), "+f"(d[2]), "+f"(d[3])
        : "r"(a[0]), "r"(a[1]), "r"(a[2]), "r"(a[3]), "r"(b0), "r"(b1));
}
// A tile accessors (linear row-major, hi at row, lo at row+32)
__device__ __forceinline__ void putsplit(unsigned char* A, int row, int k, float v){
    __nv_bfloat16 h = __float2bfloat16(v);
    *(__nv_bfloat16*)(A + row*KPB + k*2)        = h;
    *(__nv_bfloat16*)(A + (row+32)*KPB + k*2)   = __float2bfloat16(v - __bfloat162float(h));
}
__device__ __forceinline__ float getf(const unsigned char* A, int row, int k){
    return __bfloat162float(*(const __nv_bfloat16*)(A + row*KPB + k*2))
         + __bfloat162float(*(const __nv_bfloat16*)(A + (row+32)*KPB + k*2));
}

// ---- weight prep: W[k][n] fp32 -> warp-blocked hi/lo bf16 fragment pairs ----
extern "C" __global__ void __launch_bounds__(256)
fc_conv(const float* __restrict__ Wzuu, const float* __restrict__ Wzzu,
        const float* __restrict__ Wzu,  const float* __restrict__ Wu)
{
    uint32_t idx = blockIdx.x * 256u + threadIdx.x;
    if (idx >= 9u * 32u * 64u * 32u * 2u) return;     // 1,179,648
    uint32_t reg = idx & 1u;
    uint32_t t   = (idx >> 1) & 31u;
    uint32_t nt  = (idx >> 6) & 63u;
    uint32_t ks  = (idx >> 12) & 31u;
    uint32_t g   = idx >> 17;

    const float* src;
    switch (g){
        case 0: src = Wzuu;           break;
        case 1: src = Wzzu;           break;
        case 2: src = Wzu;            break;
        case 3: src = Wu;             break;
        case 4: src = Wzuu + 262144;  break;
        case 5: src = Wzzu + 262144;  break;
        case 6: src = Wzu  + 262144;  break;
        case 7: src = Wu   + 262144;  break;
        default: src = Wzuu + 524288; break;
    }
    const uint32_t n  = nt * 8 + (t >> 2);
    const uint32_t k0 = ks * 16 + (t & 3) * 2 + reg * 8;
    const float w0 = src[k0 * H + n];
    const float w1 = src[(k0 + 1) * H + n];

    __nv_bfloat16 h0 = __float2bfloat16(w0), h1 = __float2bfloat16(w1);
    __nv_bfloat16 l0 = __float2bfloat16(w0 - __bfloat162float(h0));
    __nv_bfloat16 l1 = __float2bfloat16(w1 - __bfloat162float(h1));
    uint32_t hp = ((uint32_t)*(uint16_t*)&h1 << 16) | *(uint16_t*)&h0;
    uint32_t lp = ((uint32_t)*(uint16_t*)&l1 << 16) | *(uint16_t*)&l0;

    const uint32_t w = nt >> 1, j = nt & 1;
    const uint32_t off = (((g * 32u + ks) * 32u + w) * 1024u) + t*16u + j*8u + reg*4u;
    *(uint32_t*)(g_B + off)        = hp;
    *(uint32_t*)(g_B + off + 512u) = lp;
}

// ---- one 32-k-step slab; 2 n-tiles per warp; LDG.128 B stream, pointer-inc ----
__device__ __forceinline__ void sweep_slab(const unsigned char* __restrict__ gB,
                                           uint32_t sbA, int abase, int wid, int lane,
                                           float acc[2][2][4])
{
    const unsigned char* pB = gB + (size_t)wid * 1024u + (size_t)lane * 16u;
    uint4 cH = *(const uint4*)pB;
    uint4 cL = *(const uint4*)(pB + 512u);

    const uint32_t rsel  = (uint32_t)(lane & 15);
    const uint32_t chalf = (uint32_t)((lane >> 4) * 16);
    const uint32_t aoff  = sbA + (uint32_t)(abase + rsel) * KPB + chalf;

#pragma unroll 2
    for (int ks = 0; ks < 32; ++ks){
        pB += 32768u;
        const uint4 nH = *(const uint4*)pB;          // depth-1 prefetch
        const uint4 nL = *(const uint4*)(pB + 512u);

        uint32_t Ah0[4], Ah1[4], Al0[4], Al1[4];
        const uint32_t cb = (uint32_t)(ks * 32);
        ldmA(Ah0, aoff + cb);
        ldmA(Ah1, aoff + 16*KPB + cb);
        ldmA(Al0, aoff + 32*KPB + cb);
        ldmA(Al1, aoff + 48*KPB + cb);

        mmabf(acc[0][0], Ah0, cH.x, cH.y);
        mmabf(acc[1][0], Ah1, cH.x, cH.y);
        mmabf(acc[0][1], Ah0, cH.z, cH.w);
        mmabf(acc[1][1], Ah1, cH.z, cH.w);
        mmabf(acc[0][0], Al0, cH.x, cH.y);
        mmabf(acc[1][0], Al1, cH.x, cH.y);
        mmabf(acc[0][1], Al0, cH.z, cH.w);
        mmabf(acc[1][1], Al1, cH.z, cH.w);
        mmabf(acc[0][0], Ah0, cL.x, cL.y);
        mmabf(acc[1][0], Ah1, cL.x, cL.y);
        mmabf(acc[0][1], Ah0, cL.z, cL.w);
        mmabf(acc[1][1], Ah1, cL.z, cL.w);

        cH = nH; cL = nL;
    }
}

// ---- main fused kernel ----
extern "C" __global__ void __launch_bounds__(NT, 1)
fc_main(const float* __restrict__ coords,
        const float* __restrict__ Wu0,  const float* __restrict__ bu0,
        const float* __restrict__ bu,   const float* __restrict__ bzuu,
        const float* __restrict__ Wyuu0,const float* __restrict__ byuu0,
        const float* __restrict__ Wyuu, const float* __restrict__ byuu,
        const float* __restrict__ Wzyu, const float* __restrict__ Wzyu_last,
        const float* __restrict__ Wzu0, const float* __restrict__ bzu0,
        const float* __restrict__ bzu,  const float* __restrict__ Wzzu_last,
        const float* __restrict__ Wzu_last, const float* __restrict__ bzu_last,
        const float* __restrict__ pp, const float* __restrict__ ppu,
        const float* __restrict__ ppzu,
        float* __restrict__ out, int Npts)
{
    extern __shared__ __align__(16) unsigned char smem[];
    float* sc   = (float*)(smem + SM_SC);
    float* syy  = (float*)(smem + SM_SYY);
    float* sred = (float*)(smem + SM_SRED);
    unsigned char* A = smem + SM_A;
    const uint32_t sbA = s2u(smem) + SM_A;

    const int tid = threadIdx.x, wid = tid >> 5, lane = tid & 31;
    const int m0 = blockIdx.x * MT;
    const float P = 10.f * pp[0], PU = 10.f * ppu[0], PZU = 10.f * ppzu[0];

    if (tid < 128){
        int gi = m0 * 4 + tid;
        sc[tid] = (gi < Npts * 4) ? coords[gi] : 0.f;
    }
    __syncthreads();

    // stage 0: A bands (u hi/lo rows 0/32, z hi/lo rows 64/96)
    {
        const int m = tid & 31, c0 = (tid >> 5) * 16;
        const float a0 = sc[m*4], a1 = sc[m*4+1], a2 = sc[m*4+2], y = sc[m*4+3];
        const float ys = y * (a0*Wyuu0[0] + a1*Wyuu0[1] + a2*Wyuu0[2] + byuu0[0]);
        for (int n = c0; n < c0 + 16; ++n){
            float zv = fmaxf(P *(a0*Wzu0[n] + a1*Wzu0[H+n] + a2*Wzu0[2*H+n] + bzu0[n] + ys*Wzyu[n]), 0.f);
            float uv = fmaxf(PU*(a0*Wu0[n]  + a1*Wu0[H+n]  + a2*Wu0[2*H+n]  + bu0[n]), 0.f);
            putsplit(A, m, n, uv);
            putsplit(A, 64 + m, n, zv);
        }
    }
    __syncthreads();

    // 7 sweeps: G(gate) / Z(z-update, 2 slabs) / U(u-update), x2 stages, + final gate
    const signed char sw_type[7] = {0, 2, 3, 0, 2, 3, 4};
    const signed char sw_g[7]    = {0, 1, 3, 4, 5, 7, 8};
    const signed char sw_st[7]   = {0, 0, 0, 1, 1, 1, 2};

    for (int s = 0; s < 7; ++s){
        const int type = sw_type[s];
        const int st   = sw_st[s];
        const unsigned char* gB = g_B + (size_t)sw_g[s] * 1048576u;

        float acc[2][2][4];
#pragma unroll
        for (int m = 0; m < 2; ++m)
#pragma unroll
            for (int j = 0; j < 2; ++j)
#pragma unroll
                for (int e = 0; e < 4; ++e) acc[m][j][e] = 0.f;

        if (type == 2){
            sweep_slab(gB,            sbA, 64, wid, lane, acc);   // zz @ Wzzu
            sweep_slab(gB + 1048576u, sbA, 0,  wid, lane, acc);   // + u @ Wzu
        } else {
            sweep_slab(gB, sbA, 0, wid, lane, acc);               // u @ W*
        }
        __syncthreads();    // all warps done reading A

        // in-register epilogue: thread owns rows {r0,r0+8}+16m, cols wid*16+j*8+(lane&3)*2+{0,1}
        const int r0 = lane >> 2, cb = (lane & 3) * 2;
#pragma unroll
        for (int m = 0; m < 2; ++m){
#pragma unroll
            for (int j = 0; j < 2; ++j){
#pragma unroll
                for (int e = 0; e < 4; ++e){
                    const int row = m*16 + r0 + (e >> 1) * 8;
                    const int n   = wid*16 + j*8 + cb + (e & 1);
                    const float d = acc[m][j][e];
                    if (type == 0 || type == 4){
                        float gt = fmaxf(PZU * (d + bzuu[st*H + n]), 0.f);
                        putsplit(A, 64 + row, n, getf(A, 64 + row, n) * gt);
                    } else if (type == 2){
                        float t2 = d + bzu[st*H + n] + syy[row] * Wzyu[(st + 1)*H + n];
                        putsplit(A, 64 + row, n, fmaxf(P * t2, 0.f));
                    } else {
                        putsplit(A, row, n, fmaxf(PU * (d + bu[st*H + n]), 0.f));
                    }
                }
            }
        }
        if (type == 0){      // y-term partial dot over (unchanged) u
            const int seg = tid & 31, mm = tid >> 5;
            float ps = 0.f;
#pragma unroll 8
            for (int jj = 0; jj < 16; ++jj){
                const int k = seg + 32*jj;
                ps += getf(A, mm, k) * Wyuu[st*H + k];
            }
            sred[seg*32 + mm] = ps;
        }
        __syncthreads();
        if (type == 0 && tid < 32){
            float ssum = 0.f;
#pragma unroll
            for (int sg = 0; sg < 32; ++sg) ssum += sred[sg*32 + tid];
            syy[tid] = sc[tid*4 + 3] * (ssum + byuu[st]);
        }
        __syncthreads();
    }

    // final dots: p1 = zz.Wzzu_last, p2 = u.Wzu_last, p3 = u.Wyuu[2]
    {
        const int seg = tid & 31, mm = tid >> 5;
        float p1 = 0.f, p2 = 0.f, p3 = 0.f;
#pragma unroll 8
        for (int jj = 0; jj < 16; ++jj){
            const int k = seg + 32*jj;
            const float uk = getf(A, mm, k), zk = getf(A, 64 + mm, k);
            p1 += zk * Wzzu_last[k];
            p2 += uk * Wzu_last[k];
            p3 += uk * Wyuu[2*H + k];
        }
        sred[seg*32 + mm]         = p1;
        sred[1024 + seg*32 + mm]  = p2;
        sred[2048 + seg*32 + mm]  = p3;
        __syncthreads();
        if (tid < 32 && m0 + tid < Npts){
            float s1 = 0.f, s2 = 0.f, s3 = 0.f;
#pragma unroll
            for (int sg = 0; sg < 32; ++sg){
                s1 += sred[sg*32 + tid];
                s2 += sred[1024 + sg*32 + tid];
                s3 += sred[2048 + sg*32 + tid];
            }
            out[m0 + tid] = s1 + s2 + bzu_last[0]
                          + sc[tid*4 + 3] * (s3 + byuu[2]) * Wzyu_last[0];
        }
    }
}

extern "C" void kernel_launch(void* const* d_in, const int* in_sizes, int n_in,
                              void* d_out, int out_size)
{
    const float* coords    = (const float*)d_in[0];
    const float* Wu0       = (const float*)d_in[1];
    const float* bu0       = (const float*)d_in[2];
    const float* Wu        = (const float*)d_in[3];
    const float* bu        = (const float*)d_in[4];
    const float* Wzuu      = (const float*)d_in[5];
    const float* bzuu      = (const float*)d_in[6];
    const float* Wzzu      = (const float*)d_in[7];
    const float* Wzzu_last = (const float*)d_in[8];
    const float* Wyuu0     = (const float*)d_in[9];
    const float* byuu0     = (const float*)d_in[10];
    const float* Wyuu      = (const float*)d_in[11];
    const float* byuu      = (const float*)d_in[12];
    const float* Wzyu      = (const float*)d_in[13];
    const float* Wzyu_last = (const float*)d_in[14];
    const float* Wzu0      = (const float*)d_in[15];
    const float* bzu0      = (const float*)d_in[16];
    const float* Wzu       = (const float*)d_in[17];
    const float* bzu       = (const float*)d_in[18];
    const float* Wzu_last  = (const float*)d_in[19];
    const float* bzu_last  = (const float*)d_in[20];
    const float* pp        = (const float*)d_in[21];
    const float* ppu       = (const float*)d_in[22];
    const float* ppzu      = (const float*)d_in[23];
    float* out = (float*)d_out;

    const int N = in_sizes[0] / 4;
    fc_conv<<<(9 * 131072 + 255) / 256, 256>>>(Wzuu, Wzzu, Wzu, Wu);

    cudaFuncSetAttribute(fc_main, cudaFuncAttributeMaxDynamicSharedMemorySize, SM_TOTAL);
    fc_main<<<(N + MT - 1) / MT, NT, SM_TOTAL>>>(
        coords, Wu0, bu0, bu, bzuu, Wyuu0, byuu0, Wyuu, byuu,
        Wzyu, Wzyu_last, Wzu0, bzu0, bzu, Wzzu_last, Wzu_last, bzu_last,
        pp, ppu, ppzu, out, N);
}